// round 5
// baseline (speedup 1.0000x reference)
#include <cuda_runtime.h>

// Problem constants
#define IN_SZ   8192
#define OUT_SZ  8192
#define OUT4    (OUT_SZ / 4)            // 2048 float4 columns
// sigmoid(2.0)
#define SIG_TAU 0.8807970779778823f

// Main-kernel tiling
#define THREADS          256
#define COLS4_PER_BLOCK  256            // one float4 column per thread
#define GRID_X           (OUT4 / COLS4_PER_BLOCK)   // 8
#define NSLICE           32             // split-K row slices (small -> tiny partials)
#define ROWS_PER_SLICE   (IN_SZ / NSLICE)           // 256

// Deterministic split-K scratch (no atomics -> bitwise-reproducible spikes). 1 MB.
__device__ float g_partial[NSLICE * OUT_SZ];

// Fused pass over the [IN_SZ, OUT_SZ] plane (plain loads — .cs hints measured slower):
//   - J_out = SIG_TAU * J + x[i]          (elementwise, 512 MB of the 768 MB total)
//   - acc[j] += x[i] * W[i][j]            (split-K partial GEMV, 256 MB read)
__global__ __launch_bounds__(THREADS)
void ostl_main_kernel(const float* __restrict__ x,
                      const float* __restrict__ J,
                      const float* __restrict__ W,
                      float* __restrict__ Jout)
{
    __shared__ float sx[ROWS_PER_SLICE];

    const int c    = blockIdx.x * COLS4_PER_BLOCK + threadIdx.x;  // float4 column
    const int row0 = blockIdx.y * ROWS_PER_SLICE;

    for (int i = threadIdx.x; i < ROWS_PER_SLICE; i += THREADS)
        sx[i] = x[row0 + i];
    __syncthreads();

    const float4* __restrict__ W4 = (const float4*)W;
    const float4* __restrict__ J4 = (const float4*)J;
    float4*       __restrict__ O4 = (float4*)Jout;

    float4 acc = make_float4(0.f, 0.f, 0.f, 0.f);
    int idx = row0 * OUT4 + c;   // max ~16.7M -> fits int

    #pragma unroll 8
    for (int r = 0; r < ROWS_PER_SLICE; ++r, idx += OUT4) {
        const float xi = sx[r];
        const float4 w = W4[idx];
        const float4 j = J4[idx];

        acc.x = fmaf(xi, w.x, acc.x);
        acc.y = fmaf(xi, w.y, acc.y);
        acc.z = fmaf(xi, w.z, acc.z);
        acc.w = fmaf(xi, w.w, acc.w);

        float4 o;
        o.x = fmaf(SIG_TAU, j.x, xi);
        o.y = fmaf(SIG_TAU, j.y, xi);
        o.z = fmaf(SIG_TAU, j.z, xi);
        o.w = fmaf(SIG_TAU, j.w, xi);
        O4[idx] = o;
    }

    // Deterministic per-slice partial store (coalesced float4)
    ((float4*)g_partial)[blockIdx.y * OUT4 + c] = acc;
}

// Epilogue: reduce 32 x 8192 partials (1 MB), apply LIF update, emit u_out and s.
// One thread per float4 column; 32 fully-unrolled slice loads -> per-thread MLP
// covers DRAM latency; 2048 threads spread over 64 SMs put the whole 1 MB in
// flight at once. Fixed per-thread sum order -> bitwise deterministic.
#define EPI_TPB   32
#define EPI_GRID  (OUT4 / EPI_TPB)     // 64 blocks
__global__ __launch_bounds__(EPI_TPB, 1)
void ostl_epilogue_kernel(const float* __restrict__ u,
                          float* __restrict__ out_u,
                          float* __restrict__ out_s)
{
    const int c = blockIdx.x * EPI_TPB + threadIdx.x;   // float4 column 0..2047

    const float4* __restrict__ P4 = (const float4*)g_partial;

    float4 a = make_float4(0.f, 0.f, 0.f, 0.f);
    #pragma unroll
    for (int k = 0; k < NSLICE; ++k) {                  // 32 independent loads
        const float4 p = P4[k * OUT4 + c];              // warp reads 512B lines
        a.x += p.x; a.y += p.y; a.z += p.z; a.w += p.w;
    }

    const float4 uu = ((const float4*)u)[c];
    float4 uo, so;
    {
        float un;
        un = fmaf(SIG_TAU, uu.x, a.x); so.x = (un - 1.0f) > 0.f ? 1.f : 0.f; uo.x = un - so.x;
        un = fmaf(SIG_TAU, uu.y, a.y); so.y = (un - 1.0f) > 0.f ? 1.f : 0.f; uo.y = un - so.y;
        un = fmaf(SIG_TAU, uu.z, a.z); so.z = (un - 1.0f) > 0.f ? 1.f : 0.f; uo.z = un - so.z;
        un = fmaf(SIG_TAU, uu.w, a.w); so.w = (un - 1.0f) > 0.f ? 1.f : 0.f; uo.w = un - so.w;
    }
    ((float4*)out_u)[c] = uo;
    ((float4*)out_s)[c] = so;
}

extern "C" void kernel_launch(void* const* d_in, const int* in_sizes, int n_in,
                              void* d_out, int out_size)
{
    const float* x = (const float*)d_in[0];
    const float* u = (const float*)d_in[1];
    const float* J = (const float*)d_in[2];
    const float* W = (const float*)d_in[3];

    float* out   = (float*)d_out;
    float* out_u = out;                                   // [0, 8192)
    float* out_J = out + OUT_SZ;                          // [8192, 8192+64M)
    float* out_s = out + OUT_SZ + (size_t)IN_SZ * OUT_SZ; // last 8192

    dim3 grid(GRID_X, NSLICE);
    ostl_main_kernel<<<grid, THREADS>>>(x, J, W, out_J);
    ostl_epilogue_kernel<<<EPI_GRID, EPI_TPB>>>(u, out_u, out_s);
}

// round 6
// speedup vs baseline: 1.2023x; 1.2023x over previous
#include <cuda_runtime.h>

// Problem constants
#define IN_SZ   8192
#define OUT_SZ  8192
#define OUT4    (OUT_SZ / 4)            // 2048 float4 columns
// sigmoid(2.0)
#define SIG_TAU 0.8807970779778823f

// Main-kernel tiling — known-good config (R3/R4: ~122.7us), do not change.
#define THREADS          256
#define COLS4_PER_BLOCK  256            // one float4 column per thread
#define GRID_X           (OUT4 / COLS4_PER_BLOCK)   // 8
#define NSLICE           128            // split-K row slices
#define ROWS_PER_SLICE   (IN_SZ / NSLICE)           // 64

// Deterministic split-K scratch (no atomics -> bitwise-reproducible spikes). 4 MB.
__device__ float g_partial[NSLICE * OUT_SZ];

// Fused pass over the [IN_SZ, OUT_SZ] plane (plain loads — .cs hints measured slower):
//   - J_out = SIG_TAU * J + x[i]          (elementwise, 512 MB of the 768 MB total)
//   - acc[j] += x[i] * W[i][j]            (split-K partial GEMV, 256 MB read)
__global__ __launch_bounds__(THREADS, 1)
void ostl_main_kernel(const float* __restrict__ x,
                      const float* __restrict__ J,
                      const float* __restrict__ W,
                      float* __restrict__ Jout)
{
    __shared__ float sx[ROWS_PER_SLICE];

    const int c    = blockIdx.x * COLS4_PER_BLOCK + threadIdx.x;  // float4 column
    const int row0 = blockIdx.y * ROWS_PER_SLICE;

    for (int i = threadIdx.x; i < ROWS_PER_SLICE; i += THREADS)
        sx[i] = x[row0 + i];
    __syncthreads();

    const float4* __restrict__ W4 = (const float4*)W;
    const float4* __restrict__ J4 = (const float4*)J;
    float4*       __restrict__ O4 = (float4*)Jout;

    float4 acc = make_float4(0.f, 0.f, 0.f, 0.f);
    int idx = row0 * OUT4 + c;   // max ~16.7M -> fits int

    #pragma unroll 4
    for (int r = 0; r < ROWS_PER_SLICE; ++r, idx += OUT4) {
        const float xi = sx[r];
        const float4 w = W4[idx];
        const float4 j = J4[idx];

        acc.x = fmaf(xi, w.x, acc.x);
        acc.y = fmaf(xi, w.y, acc.y);
        acc.z = fmaf(xi, w.z, acc.z);
        acc.w = fmaf(xi, w.w, acc.w);

        float4 o;
        o.x = fmaf(SIG_TAU, j.x, xi);
        o.y = fmaf(SIG_TAU, j.y, xi);
        o.z = fmaf(SIG_TAU, j.z, xi);
        o.w = fmaf(SIG_TAU, j.w, xi);
        O4[idx] = o;
    }

    // Deterministic per-slice partial store (coalesced float4)
    ((float4*)g_partial)[blockIdx.y * OUT4 + c] = acc;
}

// Epilogue: reduce 128 x 8192 partials (4 MB), apply LIF update, emit u_out, s.
// 256 blocks x 256 threads = 64K threads: 32 threads per float4 column, 4 slices
// each (fully unrolled) -> the ENTIRE 4 MB is in flight at once => BW-bound.
// 32-way combine through shared memory in a fixed order -> bitwise deterministic.
#define EPI_THREADS 256
#define EPI_COLS4   8                         // float4 columns per block
#define EPI_QGROUPS 32                        // threads per column
#define EPI_SLICES  (NSLICE / EPI_QGROUPS)    // 4 slices per thread
#define EPI_GRID    (OUT4 / EPI_COLS4)        // 256 blocks
__global__ __launch_bounds__(EPI_THREADS, 1)
void ostl_epilogue_kernel(const float* __restrict__ u,
                          float* __restrict__ out_u,
                          float* __restrict__ out_s)
{
    __shared__ float4 sacc[EPI_QGROUPS - 1][EPI_COLS4];

    const int lc = threadIdx.x & (EPI_COLS4 - 1);    // local float4 column 0..7
    const int q  = threadIdx.x >> 3;                 // slice group 0..31
    const int c  = blockIdx.x * EPI_COLS4 + lc;

    const float4* __restrict__ P4 = (const float4*)g_partial;

    float4 a = make_float4(0.f, 0.f, 0.f, 0.f);
    int idx = (q * EPI_SLICES) * OUT4 + c;
    #pragma unroll
    for (int k = 0; k < EPI_SLICES; ++k, idx += OUT4) {   // 4 independent loads
        const float4 p = P4[idx];
        a.x += p.x; a.y += p.y; a.z += p.z; a.w += p.w;
    }

    if (q > 0) sacc[q - 1][lc] = a;
    __syncthreads();

    if (q == 0) {
        #pragma unroll
        for (int t = 0; t < EPI_QGROUPS - 1; ++t) {       // fixed combine order
            const float4 b = sacc[t][lc];
            a.x += b.x; a.y += b.y; a.z += b.z; a.w += b.w;
        }
        const float4 uu = ((const float4*)u)[c];
        float4 uo, so;
        {
            float un;
            un = fmaf(SIG_TAU, uu.x, a.x); so.x = (un - 1.0f) > 0.f ? 1.f : 0.f; uo.x = un - so.x;
            un = fmaf(SIG_TAU, uu.y, a.y); so.y = (un - 1.0f) > 0.f ? 1.f : 0.f; uo.y = un - so.y;
            un = fmaf(SIG_TAU, uu.z, a.z); so.z = (un - 1.0f) > 0.f ? 1.f : 0.f; uo.z = un - so.z;
            un = fmaf(SIG_TAU, uu.w, a.w); so.w = (un - 1.0f) > 0.f ? 1.f : 0.f; uo.w = un - so.w;
        }
        ((float4*)out_u)[c] = uo;
        ((float4*)out_s)[c] = so;
    }
}

extern "C" void kernel_launch(void* const* d_in, const int* in_sizes, int n_in,
                              void* d_out, int out_size)
{
    const float* x = (const float*)d_in[0];
    const float* u = (const float*)d_in[1];
    const float* J = (const float*)d_in[2];
    const float* W = (const float*)d_in[3];

    float* out   = (float*)d_out;
    float* out_u = out;                                   // [0, 8192)
    float* out_J = out + OUT_SZ;                          // [8192, 8192+64M)
    float* out_s = out + OUT_SZ + (size_t)IN_SZ * OUT_SZ; // last 8192

    dim3 grid(GRID_X, NSLICE);
    ostl_main_kernel<<<grid, THREADS>>>(x, J, W, out_J);
    ostl_epilogue_kernel<<<EPI_GRID, EPI_THREADS>>>(u, out_u, out_s);
}